// round 12
// baseline (speedup 1.0000x reference)
#include <cuda_runtime.h>
#include <cstdint>

// Local covariance: out = boxmean5( (center(x)-boxmean5(x)) * (center(y)-boxmean5(y)) )
// x,y: [16,1,1024,1024] f32 -> out: [16,1,1016,1016] f32
//
// R12: R10 (register rings + shuffles + per-warp cp.async depth-8 SMEM ring)
// with the first 10 rows peeled (compile-time rrp -> all warmup gating folds)
// and a condition-free steady-state loop. Streaming stores, no barriers.

#define H  1024
#define W  1024
#define OH 1016
#define OW 1016
#define NB 16

#define CPWARP 120            // valid output cols per warp (128 raw - 8 halo)
#define NCS    9              // ceil(1016/120)
#define ORS    67             // output rows per strip
#define IRS    75             // input rows per strip (= ORS + 8, multiple of 5)
#define NRS    16             // 16*67 = 1072 >= 1016
#define DEPTH  8              // cp.async pipeline depth (rows in flight)

__device__ __forceinline__ void cp16(uint32_t dst, const void* src, uint32_t zf)
{
    // 16-byte async copy; zf==0 -> zero-fill (no global read)
    asm volatile("cp.async.cg.shared.global [%0], [%1], 16, %2;\n"
                 :: "r"(dst), "l"(src), "r"(zf) : "memory");
}

__global__ __launch_bounds__(128, 4)
void cov_kernel(const float* __restrict__ x,
                const float* __restrict__ y,
                float* __restrict__ out)
{
    // per-warp ring: DEPTH stages x (32 lanes x 16B x + 32 lanes x 16B y) = 1KB/stage
    __shared__ __align__(16) float4 ring[4][DEPTH][64];

    const int lane = threadIdx.x & 31;
    const int wrp  = threadIdx.x >> 5;

    const int cs = blockIdx.x;               // column strip 0..8
    const int rs = blockIdx.y * 4 + wrp;     // row strip 0..15
    const int b  = blockIdx.z;

    const int c0 = cs * CPWARP + lane * 4;   // first raw col of lane
    const int r0 = rs * ORS;                 // first input row of strip

    const float* __restrict__ xb = x + (long)b * (H * W);
    const float* __restrict__ yb = y + (long)b * (H * W);
    float*       __restrict__ ob = out + (long)b * (OH * OW);

    const bool colok = (c0 < W);
    const int  cc    = colok ? c0 : 0;                 // clamped col (address safety)
    const bool outok = (lane < 30) && (c0 < OW);
    const float inv25 = 1.0f / 25.0f;

    const uint32_t zfc = colok ? 16u : 0u;
    const uint32_t sb  = (uint32_t)__cvta_generic_to_shared(&ring[wrp][0][0]);
    const uint32_t sll = lane * 16;

    // ---- prime pipeline: rows r0 .. r0+DEPTH-1 into stages 0..DEPTH-1 ----
    #pragma unroll
    for (int d = 0; d < DEPTH; ++d) {
        const int row = r0 + d;
        const int rL  = row < H ? row : (H - 1);
        const uint32_t zf = (row < H) ? zfc : 0u;
        const uint32_t dst = sb + ((uint32_t)d << 10) + sll;
        cp16(dst,       xb + (long)rL * W + cc, zf);
        cp16(dst + 512, yb + (long)rL * W + cc, zf);
        asm volatile("cp.async.commit_group;" ::: "memory");
    }

    // register ring buffers (constant-indexed via compile-time PH)
    float xr[5][4], yr[5][4], hpr[5][4];
    float vsx[4], vsy[4], vhp[4];
    #pragma unroll
    for (int s = 0; s < 5; ++s)
        #pragma unroll
        for (int i = 0; i < 4; ++i) { xr[s][i] = 0.f; yr[s][i] = 0.f; hpr[s][i] = 0.f; }
    #pragma unroll
    for (int i = 0; i < 4; ++i) { vsx[i] = 0.f; vsy[i] = 0.f; vhp[i] = 0.f; }

    float* op = ob + (long)r0 * OW + c0;     // running output pointer (first store row = r0)

// One row of the pipeline. RRP: row index in strip (may be runtime in steady
// loop). PH: compile-time phase (ring slots). GATE: fold-away warmup gating.
// STORE: emit the store path.
#define PHASE_BODY(RRP, PH, GATE, STORE)                                        \
    {                                                                           \
        const int rrp_ = (RRP);                                                 \
        const int st_  = rrp_ & (DEPTH - 1);                                    \
        asm volatile("cp.async.wait_group 7;" ::: "memory");                    \
        float4 xv_ = ring[wrp][st_][lane];                                      \
        float4 yv_ = ring[wrp][st_][32 + lane];                                 \
        /* refill same stage with row rrp+DEPTH */                              \
        {                                                                       \
            const int row_ = r0 + rrp_ + DEPTH;                                 \
            const int rL_  = row_ < H ? row_ : (H - 1);                         \
            const uint32_t zf_ = ((rrp_ + DEPTH) < IRS && row_ < H) ? zfc : 0u; \
            const uint32_t dst_ = sb + ((uint32_t)st_ << 10) + sll;             \
            cp16(dst_,       xb + (long)rL_ * W + cc, zf_);                     \
            cp16(dst_ + 512, yb + (long)rL_ * W + cc, zf_);                     \
            asm volatile("cp.async.commit_group;" ::: "memory");                \
        }                                                                       \
        float xa_[4] = {xv_.x, xv_.y, xv_.z, xv_.w};                            \
        float ya_[4] = {yv_.x, yv_.y, yv_.z, yv_.w};                            \
        _Pragma("unroll")                                                       \
        for (int i = 0; i < 4; ++i) {                                           \
            vsx[i] += xa_[i] - xr[(PH) % 5][i]; xr[(PH) % 5][i] = xa_[i];       \
            vsy[i] += ya_[i] - yr[(PH) % 5][i]; yr[(PH) % 5][i] = ya_[i];       \
        }                                                                       \
        float nx_[4], ny_[4];                                                   \
        _Pragma("unroll")                                                       \
        for (int i = 0; i < 4; ++i) {                                           \
            nx_[i] = __shfl_down_sync(0xffffffffu, vsx[i], 1);                  \
            ny_[i] = __shfl_down_sync(0xffffffffu, vsy[i], 1);                  \
        }                                                                       \
        float bx_[4], by_[4];                                                   \
        {                                                                       \
            float t_ = (vsx[0] + vsx[1]) + (vsx[2] + vsx[3]);                   \
            bx_[0] = t_ + nx_[0];                                               \
            bx_[1] = bx_[0] - vsx[0] + nx_[1];                                  \
            bx_[2] = bx_[1] - vsx[1] + nx_[2];                                  \
            bx_[3] = bx_[2] - vsx[2] + nx_[3];                                  \
            t_ = (vsy[0] + vsy[1]) + (vsy[2] + vsy[3]);                         \
            by_[0] = t_ + ny_[0];                                               \
            by_[1] = by_[0] - vsy[0] + ny_[1];                                  \
            by_[2] = by_[1] - vsy[1] + ny_[2];                                  \
            by_[3] = by_[2] - vsy[2] + ny_[3];                                  \
        }                                                                       \
        const int sc_ = ((PH) + 3) % 5;                                         \
        float cx_[4], cy_[4];                                                   \
        cx_[0] = xr[sc_][2]; cx_[1] = xr[sc_][3];                               \
        cx_[2] = __shfl_down_sync(0xffffffffu, xr[sc_][0], 1);                  \
        cx_[3] = __shfl_down_sync(0xffffffffu, xr[sc_][1], 1);                  \
        cy_[0] = yr[sc_][2]; cy_[1] = yr[sc_][3];                               \
        cy_[2] = __shfl_down_sync(0xffffffffu, yr[sc_][0], 1);                  \
        cy_[3] = __shfl_down_sync(0xffffffffu, yr[sc_][1], 1);                  \
        float pc_[4];                                                           \
        _Pragma("unroll")                                                       \
        for (int i = 0; i < 4; ++i)                                             \
            pc_[i] = (cx_[i] - bx_[i] * inv25) * (cy_[i] - by_[i] * inv25);     \
        float np_[4];                                                           \
        _Pragma("unroll")                                                       \
        for (int i = 0; i < 4; ++i)                                             \
            np_[i] = __shfl_down_sync(0xffffffffu, pc_[i], 1);                  \
        float hp0_, hp1_, hp2_, hp3_;                                           \
        {                                                                       \
            float t_ = (pc_[0] + pc_[1]) + (pc_[2] + pc_[3]);                   \
            hp0_ = t_ + np_[0];                                                 \
            hp1_ = hp0_ - pc_[0] + np_[1];                                      \
            hp2_ = hp1_ - pc_[1] + np_[2];                                      \
            hp3_ = hp2_ - pc_[2] + np_[3];                                      \
        }                                                                       \
        if (GATE) {                                                             \
            if (rrp_ < 4) { hp0_ = 0.f; hp1_ = 0.f; hp2_ = 0.f; hp3_ = 0.f; }   \
        }                                                                       \
        vhp[0] += hp0_ - hpr[(PH) % 5][0]; hpr[(PH) % 5][0] = hp0_;             \
        vhp[1] += hp1_ - hpr[(PH) % 5][1]; hpr[(PH) % 5][1] = hp1_;             \
        vhp[2] += hp2_ - hpr[(PH) % 5][2]; hpr[(PH) % 5][2] = hp2_;             \
        vhp[3] += hp3_ - hpr[(PH) % 5][3]; hpr[(PH) % 5][3] = hp3_;             \
        if (STORE) {                                                            \
            const int orow_ = r0 + rrp_ - 8;                                    \
            if (outok && orow_ < OH) {                                          \
                float4 o_ = make_float4(vhp[0] * inv25, vhp[1] * inv25,         \
                                        vhp[2] * inv25, vhp[3] * inv25);        \
                __stcs((float4*)op, o_);                                        \
            }                                                                   \
            op += OW;                                                           \
        }                                                                       \
    }

    // ---- warmup rows 0..9: rrp compile-time, gating folds away ----
    #pragma unroll
    for (int ph = 0; ph < 5; ++ph)
        PHASE_BODY(ph, ph, 1, 0)            // rows 0..4: gated, no store
    #pragma unroll
    for (int ph = 0; ph < 5; ++ph)
        PHASE_BODY(5 + ph, ph, 0, (ph >= 3)) // rows 5..9: store rows 8,9

    // ---- steady state rows 10..IRS-1: no gating, unconditional store path ----
    for (int rr = 10; rr < IRS; rr += 5) {
        #pragma unroll
        for (int ph = 0; ph < 5; ++ph)
            PHASE_BODY(rr + ph, ph, 0, 1)
    }
#undef PHASE_BODY
}

extern "C" void kernel_launch(void* const* d_in, const int* in_sizes, int n_in,
                              void* d_out, int out_size)
{
    (void)in_sizes; (void)n_in; (void)out_size;
    const float* x = (const float*)d_in[0];
    const float* y = (const float*)d_in[1];
    float* out = (float*)d_out;

    dim3 grid(NCS, NRS / 4, NB);   // 9 col strips x 16 row strips x 16 images
    cov_kernel<<<grid, 128>>>(x, y, out);
}